// round 1
// baseline (speedup 1.0000x reference)
#include <cuda_runtime.h>

#define B_ROWS   32768
#define NIN      128
#define NLAYERS  8
#define WIDTH    256
#define KFAN     16
#define TILE_R   16
#define VALS_W   (NIN + NLAYERS * WIDTH)          /* 2176 */
#define SMEM_BYTES (VALS_W * TILE_R * 4)          /* 139264 */

__global__ __launch_bounds__(256, 1)
void ffn_gather_kernel(const float* __restrict__ inputs,
                       const float* __restrict__ weights,
                       const float* __restrict__ biases,
                       const int*   __restrict__ edge_idx,
                       float*       __restrict__ out)
{
    extern __shared__ float vals[];   // [VALS_W][TILE_R], rows contiguous
    const int t    = threadIdx.x;     // 0..255 == unit id
    const int row0 = blockIdx.x * TILE_R;

    // ---- Load input tile: 16 rows x 128 feats, transposed into vals[f][r] ----
    {
        const float4* in4 = (const float4*)(inputs + (size_t)row0 * NIN);
        #pragma unroll
        for (int it = 0; it < 2; it++) {
            int i  = t + it * 256;          // 0..511
            int r  = i & (TILE_R - 1);      // row fast -> STS mostly conflict-free
            int c4 = i >> 4;                // 0..31 float4 column
            float4 v = in4[r * (NIN / 4) + c4];
            int f = c4 * 4;
            vals[(f + 0) * TILE_R + r] = v.x;
            vals[(f + 1) * TILE_R + r] = v.y;
            vals[(f + 2) * TILE_R + r] = v.z;
            vals[(f + 3) * TILE_R + r] = v.w;
        }
    }

    // ---- Prefetch layer 0 tables into registers (coalesced 128-bit loads) ----
    const int4*   idx4 = (const int4*)edge_idx;   // [(l*W+u)*4 + j]
    const float4* w4   = (const float4*)weights;
    int4   ib[4];
    float4 wb[4];
    float  bias_n;
    #pragma unroll
    for (int j = 0; j < 4; j++) {
        ib[j] = idx4[t * 4 + j];
        wb[j] = w4 [t * 4 + j];
    }
    bias_n = biases[t];

    __syncthreads();

    #pragma unroll 1
    for (int l = 0; l < NLAYERS; l++) {
        // unpack current layer tables (pre-scale index to word offset)
        int   foff[KFAN];
        float fw  [KFAN];
        #pragma unroll
        for (int j = 0; j < 4; j++) {
            foff[j*4+0] = ib[j].x * TILE_R;
            foff[j*4+1] = ib[j].y * TILE_R;
            foff[j*4+2] = ib[j].z * TILE_R;
            foff[j*4+3] = ib[j].w * TILE_R;
            fw  [j*4+0] = wb[j].x;
            fw  [j*4+1] = wb[j].y;
            fw  [j*4+2] = wb[j].z;
            fw  [j*4+3] = wb[j].w;
        }
        float bias = bias_n;

        // prefetch next layer tables while we compute this one
        if (l < NLAYERS - 1) {
            int base = (l + 1) * WIDTH + t;
            #pragma unroll
            for (int j = 0; j < 4; j++) {
                ib[j] = idx4[base * 4 + j];
                wb[j] = w4 [base * 4 + j];
            }
            bias_n = biases[base];
        }

        // gather + dot: unit t, all 16 rows
        float acc[TILE_R];
        #pragma unroll
        for (int r = 0; r < TILE_R; r++) acc[r] = bias;

        #pragma unroll
        for (int k = 0; k < KFAN; k++) {
            const float* vp = vals + foff[k];
            float wk = fw[k];
            #pragma unroll
            for (int rg = 0; rg < TILE_R / 4; rg++) {
                float4 v = *(const float4*)(vp + rg * 4);
                acc[rg*4+0] += wk * v.x;
                acc[rg*4+1] += wk * v.y;
                acc[rg*4+2] += wk * v.z;
                acc[rg*4+3] += wk * v.w;
            }
        }

        // sigmoid
        float s[TILE_R];
        #pragma unroll
        for (int r = 0; r < TILE_R; r++)
            s[r] = __fdividef(1.0f, 1.0f + __expf(-acc[r]));

        if (l == NLAYERS - 1) {
            // final layer IS the output: coalesced store, skip SMEM round-trip
            #pragma unroll
            for (int r = 0; r < TILE_R; r++)
                out[(size_t)(row0 + r) * WIDTH + t] = s[r];
        } else {
            int fo = NIN + l * WIDTH + t;     // write region disjoint from reads
            float* wp = vals + fo * TILE_R;
            #pragma unroll
            for (int rg = 0; rg < TILE_R / 4; rg++) {
                float4 v = make_float4(s[rg*4+0], s[rg*4+1], s[rg*4+2], s[rg*4+3]);
                *(float4*)(wp + rg * 4) = v;
            }
            __syncthreads();   // outputs of layer l visible before layer l+1 gathers
        }
    }
}

extern "C" void kernel_launch(void* const* d_in, const int* in_sizes, int n_in,
                              void* d_out, int out_size)
{
    const float* inputs   = (const float*)d_in[0];
    const float* weights  = (const float*)d_in[1];
    const float* biases   = (const float*)d_in[2];
    const int*   edge_idx = (const int*)  d_in[3];
    float*       out      = (float*)d_out;

    static bool attr_set = []{
        cudaFuncSetAttribute(ffn_gather_kernel,
                             cudaFuncAttributeMaxDynamicSharedMemorySize,
                             SMEM_BYTES);
        return true;
    }();
    (void)attr_set;

    ffn_gather_kernel<<<B_ROWS / TILE_R, 256, SMEM_BYTES>>>(
        inputs, weights, biases, edge_idx, out);
}

// round 15
// speedup vs baseline: 2.4227x; 2.4227x over previous
#include <cuda_runtime.h>
#include <cuda_fp16.h>

#define B_ROWS   32768
#define NIN      128
#define NLAYERS  8
#define WIDTH    256
#define KFAN     16
#define TILE_R   32
#define VALS_W   (NIN + NLAYERS * WIDTH)          /* 2176 */
#define SMEM_BYTES (VALS_W * TILE_R * 2)          /* 139264 */

__global__ __launch_bounds__(256, 1)
void ffn_gather_fp16(const float* __restrict__ inputs,
                     const float* __restrict__ weights,
                     const float* __restrict__ biases,
                     const int*   __restrict__ edge_idx,
                     float*       __restrict__ out)
{
    extern __shared__ __half vals[];              // [VALS_W][TILE_R] fp16
    __half2* vals2 = (__half2*)vals;
    const int t    = threadIdx.x;
    const int lane = t & 31;
    const int wid  = t >> 5;                      // warp 0..7: units [wid*32, wid*32+32)
    const int sub  = lane >> 4;                   // which unit of the pair
    const int j    = lane & 15;                   // half2 word -> rows 2j, 2j+1
    const int row0 = blockIdx.x * TILE_R;

    // ---- Transpose input: 32 rows x 128 feats -> vals[f][r], fp16 ----
    {
        const float4* in4 = (const float4*)(inputs + (size_t)row0 * NIN);
        #pragma unroll
        for (int it = 0; it < 4; it++) {
            int i  = t + it * 256;                // 0..1023
            int r  = i & 31;
            int c4 = i >> 5;                      // 0..31
            float4 v = in4[r * (NIN / 4) + c4];
            int f = c4 * 4;
            vals[(f + 0) * TILE_R + r] = __float2half_rn(v.x);
            vals[(f + 1) * TILE_R + r] = __float2half_rn(v.y);
            vals[(f + 2) * TILE_R + r] = __float2half_rn(v.z);
            vals[(f + 3) * TILE_R + r] = __float2half_rn(v.w);
        }
    }

    const int4*   idx4 = (const int4*)edge_idx;   // tables: [(l*256+u)*4 + q]
    const float4* w4   = (const float4*)weights;

    // ---- Prefetch tables for (l=0, pair=0, my sub) ----
    int4   ib[4];
    float4 wb[4];
    float  bs;
    {
        int g = wid * 32 + sub;
        #pragma unroll
        for (int q = 0; q < 4; q++) { ib[q] = idx4[g * 4 + q]; wb[q] = w4[g * 4 + q]; }
        bs = biases[g];
    }
    __syncthreads();

    #pragma unroll 1
    for (int l = 0; l < NLAYERS; l++) {
        #pragma unroll 1
        for (int p = 0; p < 16; p++) {
            // unpack current tables (index pre-scaled to half2-word offset)
            int   off[KFAN];
            float fw [KFAN];
            #pragma unroll
            for (int q = 0; q < 4; q++) {
                off[q*4+0] = ib[q].x * (TILE_R/2) + j;
                off[q*4+1] = ib[q].y * (TILE_R/2) + j;
                off[q*4+2] = ib[q].z * (TILE_R/2) + j;
                off[q*4+3] = ib[q].w * (TILE_R/2) + j;
                fw [q*4+0] = wb[q].x;
                fw [q*4+1] = wb[q].y;
                fw [q*4+2] = wb[q].z;
                fw [q*4+3] = wb[q].w;
            }
            float bias = bs;

            // prefetch next pair's tables
            if (!(l == NLAYERS - 1 && p == 15)) {
                int gn = (p < 15) ? (l * WIDTH + wid * 32 + 2 * (p + 1) + sub)
                                  : ((l + 1) * WIDTH + wid * 32 + sub);
                #pragma unroll
                for (int q = 0; q < 4; q++) { ib[q] = idx4[gn * 4 + q]; wb[q] = w4[gn * 4 + q]; }
                bs = biases[gn];
            }

            // gather + dot for rows (2j, 2j+1) of unit u
            float ax = bias, ay = bias;
            #pragma unroll
            for (int k = 0; k < KFAN; k++) {
                float2 v = __half22float2(vals2[off[k]]);
                ax = fmaf(fw[k], v.x, ax);
                ay = fmaf(fw[k], v.y, ay);
            }

            float s0 = __fdividef(1.0f, 1.0f + __expf(-ax));
            float s1 = __fdividef(1.0f, 1.0f + __expf(-ay));

            int u = wid * 32 + 2 * p + sub;
            if (l == NLAYERS - 1) {
                // final layer: fp32 straight to output (no re-quantization)
                out[(size_t)(row0 + 2 * j)     * WIDTH + u] = s0;
                out[(size_t)(row0 + 2 * j + 1) * WIDTH + u] = s1;
            } else {
                int fo = NIN + l * WIDTH + u;     // write region disjoint from reads
                vals2[fo * (TILE_R/2) + j] = __floats2half2_rn(s0, s1);
            }
        }
        if (l < NLAYERS - 1) __syncthreads();
    }
}

extern "C" void kernel_launch(void* const* d_in, const int* in_sizes, int n_in,
                              void* d_out, int out_size)
{
    const float* inputs   = (const float*)d_in[0];
    const float* weights  = (const float*)d_in[1];
    const float* biases   = (const float*)d_in[2];
    const int*   edge_idx = (const int*)  d_in[3];
    float*       out      = (float*)d_out;

    static bool attr_set = []{
        cudaFuncSetAttribute(ffn_gather_fp16,
                             cudaFuncAttributeMaxDynamicSharedMemorySize,
                             SMEM_BYTES);
        return true;
    }();
    (void)attr_set;

    ffn_gather_fp16<<<B_ROWS / TILE_R, 256, SMEM_BYTES>>>(
        inputs, weights, biases, edge_idx, out);
}